// round 11
// baseline (speedup 1.0000x reference)
#include <cuda_runtime.h>

// Fused: conv3d(16->32, k3, pad1) + bias + maxpool(2x2x2) + logsumexp(ch) + relu
// x: (16,16,32,64,64) f32, w: (32,16,3,3,3) f32, bias: (32) f32
// out: (16,1,16,32,32) f32
//
// Block = 256 threads = 16 oc-pairs x 16 pooled positions (tile 1x2x8 in od,oh,ow).
// Each thread computes channels (oc, oc+16) packed as f32x2, 8 conv accumulators
// (the 2x2x2 pool window).
//
// R10 vs measured R7-baseline (1574.8us, fma=51%, alu=20%, L1=68%, issue=46%):
//  - x tile stored in smem as DUPLICATED f32x2 pairs (v,v): one LDS.64 feeds FMA2
//    directly (kills the pack2 MOV per x-read, shortens the LDS->FMA chain).
//  - weights loaded in 9-pair register groups per (xd,dd) just before use:
//    54 LDS.64/ic but only 18 weight regs live -> no spill under the 128-reg cap
//    (the R7 wr[27] hoist would have spilled: ~130 live regs).

#define TOH 2
#define TOW 8
#define SMEM_X_PAIRS  (16 * 4 * 6 * 18)          // 6912 ull = 55296 B (duplicated x)
#define SMEM_W_PAIRS  (16 * 27 * 16)             // 6912 ull = 55296 B
#define SMEM_BYTES    ((SMEM_X_PAIRS + SMEM_W_PAIRS) * 8)   // 110592 B

typedef unsigned long long ull;

__device__ __forceinline__ ull pack2(float v) {
    unsigned r = __float_as_uint(v);
    ull d;
    asm("mov.b64 %0, {%1, %1};" : "=l"(d) : "r"(r));
    return d;
}

__device__ __forceinline__ void fma2(ull& a, ull b, ull c) {
    // packed dual-fp32 FMA (Blackwell f32x2 pipe)
    asm("fma.rn.f32x2 %0, %1, %2, %3;" : "=l"(a) : "l"(b), "l"(c), "l"(a));
}

__global__ __launch_bounds__(256, 2)
void conv_pool_lse_kernel(const float* __restrict__ x,
                          const float* __restrict__ w,
                          const float* __restrict__ bias,
                          float* __restrict__ out) {
    extern __shared__ char smem[];
    ull* xs = reinterpret_cast<ull*>(smem);                        // [16][4][6][18] dup-pairs
    ull* ws = reinterpret_cast<ull*>(smem) + SMEM_X_PAIRS;         // [16][27][16] oc-pairs

    const int tid = threadIdx.x;
    const int bz = blockIdx.z;
    const int b  = bz >> 4;
    const int od = bz & 15;
    const int OH0 = blockIdx.y * TOH;
    const int OW0 = blockIdx.x * TOW;

    // ---- weights into paired layout: ws[ic][tap][ocp] = (w[ocp], w[ocp+16]) ----
    {
        float* wsf = reinterpret_cast<float*>(ws);
        for (int j = tid; j < 13824; j += 256) {
            int ic  = j / 864;
            int r   = j - ic * 864;
            int tap = r >> 5;
            int r2  = r & 31;
            int ocp  = r2 >> 1;
            int half = r2 & 1;
            int oc = ocp + (half << 4);
            wsf[j] = w[oc * 432 + ic * 27 + tap];
        }
    }

    // ---- x tile (halo + zero pad) stored as duplicated f32x2: xs[ic][xd][xh][xw] ----
    {
        const int d0 = od * 2 - 1;
        const int h0 = OH0 * 2 - 1;
        const int w0 = OW0 * 2 - 1;
        const float* xb = x + (long)b * (16 * 32 * 64 * 64);
        for (int i = tid; i < SMEM_X_PAIRS; i += 256) {
            int ic = i / 432;
            int r  = i - ic * 432;
            int xd = r / 108; r -= xd * 108;
            int xh = r / 18;
            int xw = r - xh * 18;
            int gd = d0 + xd, gh = h0 + xh, gw = w0 + xw;
            float v = 0.0f;
            if ((unsigned)gd < 32u && (unsigned)gh < 64u && (unsigned)gw < 64u)
                v = xb[((ic * 32 + gd) * 64 + gh) * 64 + gw];
            xs[i] = pack2(v);
        }
    }
    __syncthreads();

    // ---- main compute ----
    const int oc  = tid & 15;          // channel pair index: channels oc and oc+16
    const int pos = tid >> 4;          // 0..15 pooled positions
    const int ph  = pos >> 3;          // 0..1
    const int pw  = pos & 7;           // 0..7
    const int ch  = ph * 2;            // conv-row base within tile
    const int cw  = pw * 2;

    ull acc[2][2][2];
#pragma unroll
    for (int i = 0; i < 2; ++i)
#pragma unroll
        for (int j = 0; j < 2; ++j)
#pragma unroll
            for (int k = 0; k < 2; ++k) acc[i][j][k] = 0ull;

#pragma unroll 1
    for (int ic = 0; ic < 16; ++ic) {
        const ull* xsl = xs + ic * 432;
        const ull* wl  = ws + ic * (27 * 16) + oc;

#pragma unroll
        for (int xd = 0; xd < 4; ++xd) {
            // 4x4 patch of duplicated x pairs at depth slice xd (LDS.64 broadcast)
            ull xp[16];
#pragma unroll
            for (int i = 0; i < 16; ++i)
                xp[i] = xsl[xd * 108 + (ch + (i >> 2)) * 18 + (cw + (i & 3))];

#pragma unroll
            for (int dd = 0; dd < 2; ++dd) {
                const int kd = xd - dd;
                if (kd < 0 || kd > 2) continue;
                // load the 9 weight pairs for this kd just before use (18 regs live)
                ull wr[9];
#pragma unroll
                for (int t = 0; t < 9; ++t) wr[t] = wl[(kd * 9 + t) * 16];
#pragma unroll
                for (int kh = 0; kh < 3; ++kh) {
#pragma unroll
                    for (int kw = 0; kw < 3; ++kw) {
                        ull wp = wr[kh * 3 + kw];
                        fma2(acc[dd][0][0], wp, xp[(kh + 0) * 4 + kw + 0]);
                        fma2(acc[dd][0][1], wp, xp[(kh + 0) * 4 + kw + 1]);
                        fma2(acc[dd][1][0], wp, xp[(kh + 1) * 4 + kw + 0]);
                        fma2(acc[dd][1][1], wp, xp[(kh + 1) * 4 + kw + 1]);
                    }
                }
            }
        }
    }

    // ---- maxpool over the 2x2x2 accumulators, + bias ----
    float m0 = -3.0e38f, m1 = -3.0e38f;
#pragma unroll
    for (int i = 0; i < 2; ++i)
#pragma unroll
        for (int j = 0; j < 2; ++j)
#pragma unroll
            for (int k = 0; k < 2; ++k) {
                ull a = acc[i][j][k];
                m0 = fmaxf(m0, __uint_as_float((unsigned)a));
                m1 = fmaxf(m1, __uint_as_float((unsigned)(a >> 32)));
            }
    m0 += bias[oc];
    m1 += bias[oc + 16];

    // ---- logsumexp over 32 channels (16 lanes x 2 channels each) + relu ----
    float m = fmaxf(m0, m1);
#pragma unroll
    for (int msk = 8; msk; msk >>= 1)
        m = fmaxf(m, __shfl_xor_sync(0xffffffffu, m, msk));
    float s = expf(m0 - m) + expf(m1 - m);
#pragma unroll
    for (int msk = 8; msk; msk >>= 1)
        s += __shfl_xor_sync(0xffffffffu, s, msk);

    if (oc == 0) {
        float r = m + logf(s);
        out[((b * 16 + od) * 32 + (OH0 + ph)) * 32 + (OW0 + pw)] = fmaxf(r, 0.0f);
    }
}

extern "C" void kernel_launch(void* const* d_in, const int* in_sizes, int n_in,
                              void* d_out, int out_size) {
    (void)in_sizes; (void)n_in; (void)out_size;
    const float* x    = (const float*)d_in[0];
    const float* w    = (const float*)d_in[1];
    const float* bias = (const float*)d_in[2];
    float* out        = (float*)d_out;

    (void)cudaFuncSetAttribute(conv_pool_lse_kernel,
                               cudaFuncAttributeMaxDynamicSharedMemorySize, SMEM_BYTES);

    dim3 grid(32 / TOW, 32 / TOH, 16 * 16);   // (ow tiles, oh tiles, b*od)
    conv_pool_lse_kernel<<<grid, 256, SMEM_BYTES>>>(x, w, bias, out);
}

// round 12
// speedup vs baseline: 1.3329x; 1.3329x over previous
#include <cuda_runtime.h>

// Fused: conv3d(16->32, k3, pad1) + bias + maxpool(2x2x2) + logsumexp(ch) + relu
// x: (16,16,32,64,64) f32, w: (32,16,3,3,3) f32, bias: (32) f32
// out: (16,1,16,32,32) f32
//
// R11 design (post-mortem of R10 regression: constraint = exposed LDS latency per
// FMA, not LDS flavor):
//  - 256 threads = 8 oc-groups x 32 pooled positions (tile 1od x 4oh x 8ow).
//  - Each thread: 4 output channels (g, g+16, g+8, g+24) as TWO f32x2 accumulator
//    sets over the 2x2x2 pool window => 2x FMA per x-load vs R0/R10.
//  - Weights: smem entry = 16B (all 4 channels of one tap) => one LDS.128 feeds
//    8 FMA2s; weight wavefronts/ic stay at 54 while FMA2/ic doubles to 432.
//  - x: plain f32 smem + pack2 MOV (measured faster than dup-pair LDS.64).

#define TOH 4
#define TOW 8
#define SMEM_X_FLOATS (16 * 4 * 10 * 18)         // 11520 floats = 46080 B
#define SMEM_W_BYTES  (16 * 27 * 8 * 16)         // 3456 x 16B   = 55296 B
#define SMEM_BYTES    (SMEM_X_FLOATS * 4 + SMEM_W_BYTES)   // 101376 B

typedef unsigned long long ull;

__device__ __forceinline__ ull pack2(float v) {
    unsigned r = __float_as_uint(v);
    ull d;
    asm("mov.b64 %0, {%1, %1};" : "=l"(d) : "r"(r));
    return d;
}

__device__ __forceinline__ void fma2(ull& a, ull b, ull c) {
    // packed dual-fp32 FMA (Blackwell f32x2 pipe)
    asm("fma.rn.f32x2 %0, %1, %2, %3;" : "=l"(a) : "l"(b), "l"(c), "l"(a));
}

__global__ __launch_bounds__(256, 2)
void conv_pool_lse_kernel(const float* __restrict__ x,
                          const float* __restrict__ w,
                          const float* __restrict__ bias,
                          float* __restrict__ out) {
    extern __shared__ char smem[];
    float* xs = reinterpret_cast<float*>(smem);                           // [16][4][10][18]
    ulonglong2* ws = reinterpret_cast<ulonglong2*>(smem + SMEM_X_FLOATS * 4); // [16][27][8]

    const int tid = threadIdx.x;
    const int bz = blockIdx.z;
    const int b  = bz >> 4;
    const int od = bz & 15;
    const int OH0 = blockIdx.y * TOH;
    const int OW0 = blockIdx.x * TOW;

    // ---- weights: ws[ic][tap][g] = 16B {w[g], w[g+16], w[g+8], w[g+24]} ----
    {
        float* wsf = reinterpret_cast<float*>(ws);
        for (int j = tid; j < 13824; j += 256) {
            int ic  = j / 864;
            int r   = j - ic * 864;
            int tap = r >> 5;
            int q   = r & 31;
            int g   = q >> 2;
            int s   = q & 3;
            int oc  = g + ((s & 1) << 4) + ((s >> 1) << 3);
            wsf[j] = w[oc * 432 + ic * 27 + tap];
        }
    }

    // ---- x tile (halo + zero pad): xs[ic][xd][xh][xw], 4x10x18 per ic ----
    {
        const int d0 = od * 2 - 1;
        const int h0 = OH0 * 2 - 1;
        const int w0 = OW0 * 2 - 1;
        const float* xb = x + (long)b * (16 * 32 * 64 * 64);
        for (int i = tid; i < SMEM_X_FLOATS; i += 256) {
            int ic = i / 720;
            int r  = i - ic * 720;
            int xd = r / 180; r -= xd * 180;
            int xh = r / 18;
            int xw = r - xh * 18;
            int gd = d0 + xd, gh = h0 + xh, gw = w0 + xw;
            float v = 0.0f;
            if ((unsigned)gd < 32u && (unsigned)gh < 64u && (unsigned)gw < 64u)
                v = xb[((ic * 32 + gd) * 64 + gh) * 64 + gw];
            xs[i] = v;
        }
    }
    __syncthreads();

    // ---- main compute ----
    const int g   = tid & 7;           // oc group: channels g, g+16 (A) and g+8, g+24 (B)
    const int pos = tid >> 3;          // 0..31 pooled positions
    const int ph  = pos >> 3;          // 0..3
    const int pw  = pos & 7;           // 0..7
    const int ch  = ph * 2;            // conv-row base within tile (0..6)
    const int cw  = pw * 2;

    ull accA[2][2][2], accB[2][2][2];
#pragma unroll
    for (int i = 0; i < 2; ++i)
#pragma unroll
        for (int j = 0; j < 2; ++j)
#pragma unroll
            for (int k = 0; k < 2; ++k) { accA[i][j][k] = 0ull; accB[i][j][k] = 0ull; }

#pragma unroll 1
    for (int ic = 0; ic < 16; ++ic) {
        const float* xsl = xs + ic * 720;
        const ulonglong2* wl = ws + ic * (27 * 8) + g;

#pragma unroll
        for (int xd = 0; xd < 4; ++xd) {
            // 4x4 patch at depth slice xd, packed to f32x2 (broadcast LDS.32)
            ull xp[16];
#pragma unroll
            for (int i = 0; i < 16; ++i)
                xp[i] = pack2(xsl[xd * 180 + (ch + (i >> 2)) * 18 + (cw + (i & 3))]);

#pragma unroll
            for (int dd = 0; dd < 2; ++dd) {
                const int kd = xd - dd;
                if (kd < 0 || kd > 2) continue;
#pragma unroll
                for (int kh = 0; kh < 3; ++kh) {
                    // one LDS.128 per tap: both channel pairs
                    ulonglong2 w0 = wl[(kd * 9 + kh * 3 + 0) * 8];
                    ulonglong2 w1 = wl[(kd * 9 + kh * 3 + 1) * 8];
                    ulonglong2 w2 = wl[(kd * 9 + kh * 3 + 2) * 8];
#pragma unroll
                    for (int kw = 0; kw < 3; ++kw) {
                        ulonglong2 wq = (kw == 0) ? w0 : (kw == 1) ? w1 : w2;
                        ull x00 = xp[(kh + 0) * 4 + kw + 0];
                        ull x01 = xp[(kh + 0) * 4 + kw + 1];
                        ull x10 = xp[(kh + 1) * 4 + kw + 0];
                        ull x11 = xp[(kh + 1) * 4 + kw + 1];
                        fma2(accA[dd][0][0], wq.x, x00);
                        fma2(accA[dd][0][1], wq.x, x01);
                        fma2(accA[dd][1][0], wq.x, x10);
                        fma2(accA[dd][1][1], wq.x, x11);
                        fma2(accB[dd][0][0], wq.y, x00);
                        fma2(accB[dd][0][1], wq.y, x01);
                        fma2(accB[dd][1][0], wq.y, x10);
                        fma2(accB[dd][1][1], wq.y, x11);
                    }
                }
            }
        }
    }

    // ---- maxpool over the 2x2x2 accumulators, + bias (4 channels/thread) ----
    float mA0 = -3.0e38f, mA1 = -3.0e38f, mB0 = -3.0e38f, mB1 = -3.0e38f;
#pragma unroll
    for (int i = 0; i < 2; ++i)
#pragma unroll
        for (int j = 0; j < 2; ++j)
#pragma unroll
            for (int k = 0; k < 2; ++k) {
                ull a = accA[i][j][k];
                ull c = accB[i][j][k];
                mA0 = fmaxf(mA0, __uint_as_float((unsigned)a));
                mA1 = fmaxf(mA1, __uint_as_float((unsigned)(a >> 32)));
                mB0 = fmaxf(mB0, __uint_as_float((unsigned)c));
                mB1 = fmaxf(mB1, __uint_as_float((unsigned)(c >> 32)));
            }
    mA0 += bias[g];
    mA1 += bias[g + 16];
    mB0 += bias[g + 8];
    mB1 += bias[g + 24];

    // ---- logsumexp over 32 channels (8 lanes x 4 channels each) + relu ----
    // Lane groups of 8 (same pos); xor masks 4,2,1 stay inside each group.
    float m = fmaxf(fmaxf(mA0, mA1), fmaxf(mB0, mB1));
#pragma unroll
    for (int msk = 4; msk; msk >>= 1)
        m = fmaxf(m, __shfl_xor_sync(0xffffffffu, m, msk));
    float s = expf(mA0 - m) + expf(mA1 - m) + expf(mB0 - m) + expf(mB1 - m);
#pragma unroll
    for (int msk = 4; msk; msk >>= 1)
        s += __shfl_xor_sync(0xffffffffu, s, msk);

    if (g == 0) {
        float r = m + logf(s);
        out[((b * 16 + od) * 32 + (OH0 + ph)) * 32 + (OW0 + pw)] = fmaxf(r, 0.0f);
    }
}

extern "C" void kernel_launch(void* const* d_in, const int* in_sizes, int n_in,
                              void* d_out, int out_size) {
    (void)in_sizes; (void)n_in; (void)out_size;
    const float* x    = (const float*)d_in[0];
    const float* w    = (const float*)d_in[1];
    const float* bias = (const float*)d_in[2];
    float* out        = (float*)d_out;

    (void)cudaFuncSetAttribute(conv_pool_lse_kernel,
                               cudaFuncAttributeMaxDynamicSharedMemorySize, SMEM_BYTES);

    dim3 grid(32 / TOW, 32 / TOH, 16 * 16);   // (4 ow tiles, 8 oh tiles, b*od)
    conv_pool_lse_kernel<<<grid, 256, SMEM_BYTES>>>(x, w, bias, out);
}